// round 9
// baseline (speedup 1.0000x reference)
#include <cuda_runtime.h>
#include <cuda_fp16.h>
#include <cstdint>
#include <cstring>

// Problem dims
#define FIN   4096
#define FOUT  4096
#define MTOT  4096   // 2 * 2048

// GEMM tiling: CTA computes 128(M) x 256(N), K-chunk = 64
#define BM 128
#define BN 256
#define BK 64
#define KCHUNKS (FIN / BK)   // 64

#define NSTAGE       2                // depth 2 -> 99KB smem -> 2 CTAs/SM
#define A_BYTES      16384            // 128 rows x 128B
#define B_BYTES      32768            // 256 rows x 128B
#define STAGE_BYTES  (A_BYTES + B_BYTES)   // 49152
// SMEM layout (dynamic):
//   [0..4)     TMEM base ptr (written by tcgen05.alloc)
//   [8..40)    full[s]=8+16s, empty[s]=16+16s  (s=0..1)
//   [72..80)   done mbarrier
//   [1024 + s*49152) stage s: A tile then B tile (1024-aligned for SW128 desc)
#define SM_BAR    8
#define SM_DONE   72
#define SM_TILE0  1024
#define SMEM_BYTES (1024 + NSTAGE * STAGE_BYTES)   // 99328 -> occupancy 2

// idesc for tcgen05.mma kind::f16: dtype=F32 (bit4), atype=F16(0), btype=F16(0),
// N/8 at bit17 (256/8=32), M/16 at bit24 (128/16=8), both K-major
#define GEMM_IDESC 0x8400010u

// tcgen05 exists only in the arch-specific passes; the plain compute_103 pass
// the harness also builds gets a correct FFMA fallback so ptxas succeeds.
// At runtime the loader exact-matches the sm_103a cubin -> tcgen05 path runs.
#if defined(__CUDA_ARCH__) && \
    (defined(__CUDA_ARCH_FEAT_SM103_ALL) || defined(__CUDA_ARCH_FEAT_SM100_ALL) || \
     defined(__CUDA_ARCH_FEAT_SM101_ALL))
#define HAS_TCGEN05 1
#else
#define HAS_TCGEN05 0
#endif

// fp16 staging buffers in chunk-blocked, pre-SW128-swizzled layout:
// g_A: [mtile(32)][chunk(64)][16384B block]   block = swizzled 128x128B image
// g_B: [ntile(16)][chunk(64)][32768B block]   block = swizzled 256x128B image
__device__ __half g_A[(size_t)MTOT * FIN];
__device__ __half g_B[(size_t)FOUT * FIN];

#define SWZ(x) ((x) ^ (((x) >> 3) & 0x70))

// ---------------------------------------------------------------------------
// helpers
// ---------------------------------------------------------------------------
__device__ __forceinline__ uint32_t h2u(__half2 h) {
    uint32_t u;
    memcpy(&u, &h, 4);
    return u;
}

__device__ __forceinline__ uint32_t smem_u32(const void* p) {
    uint32_t a;
    asm("{ .reg .u64 t; cvta.to.shared.u64 t, %1; cvt.u32.u64 %0, t; }"
        : "=r"(a) : "l"(p));
    return a;
}

#if HAS_TCGEN05
__device__ __forceinline__ bool elect_one() {
    uint32_t pred;
    asm volatile(
        "{\n\t.reg .pred p;\n\t"
        "elect.sync _|p, 0xFFFFFFFF;\n\t"
        "selp.b32 %0, 1, 0, p;\n\t}"
        : "=r"(pred));
    return pred != 0;
}

// SW128 K-major smem descriptor: layout=SW128(2), version=1, SBO=64, LBO=1
static constexpr unsigned long long DESC_BASE =
    (2ULL << 61) | (1ULL << 46) | (64ULL << 32) | (1ULL << 16);

__device__ __forceinline__ uint64_t make_desc(uint32_t addr) {
    return DESC_BASE | ((uint64_t)(addr >> 4) & 0x3FFF);
}

__device__ __forceinline__ void wait_parity(uint32_t mbar, int phase) {
    asm volatile(
        "{\n\t.reg .pred P;\n\t"
        "WL%=:\n\t"
        "mbarrier.try_wait.parity.acquire.cta.shared::cta.b64 P, [%0], %1, 0x989680;\n\t"
        "@P bra.uni WD%=;\n\t"
        "bra.uni WL%=;\n\t"
        "WD%=:\n\t}"
        :: "r"(mbar), "r"((uint32_t)phase) : "memory");
}

__device__ __forceinline__ void bulk_g2s_mc(uint32_t dst, const void* src,
                                            uint32_t bytes, uint32_t mbar,
                                            uint16_t mask) {
    asm volatile(
        "cp.async.bulk.shared::cluster.global.mbarrier::complete_tx::bytes"
        ".multicast::cluster [%0], [%1], %2, [%3], %4;"
        :: "r"(dst), "l"(src), "r"(bytes), "r"(mbar), "h"(mask) : "memory");
}

__device__ __forceinline__ void mma_f16_ss(uint32_t d_tmem, uint64_t a_desc,
                                           uint64_t b_desc, uint32_t en) {
    asm volatile(
        "{\n\t.reg .pred p;\n\t"
        "setp.ne.u32 p, %5, 0;\n\t"
        "tcgen05.mma.cta_group::1.kind::f16 [%0], %1, %2, %3, {%4, %4, %4, %4}, p;\n\t}"
        :: "r"(d_tmem), "l"(a_desc), "l"(b_desc), "r"(GEMM_IDESC),
           "r"(0u), "r"(en)
        : "memory");
}

__device__ __forceinline__ void ldtm_x32(uint32_t* r, uint32_t tmem_addr) {
    asm volatile(
        "tcgen05.ld.sync.aligned.32x32b.x32.b32 "
        "{%0, %1, %2, %3, %4, %5, %6, %7, "
        " %8, %9, %10, %11, %12, %13, %14, %15, "
        " %16, %17, %18, %19, %20, %21, %22, %23, "
        " %24, %25, %26, %27, %28, %29, %30, %31}, [%32];"
        : "=r"(r[0]),  "=r"(r[1]),  "=r"(r[2]),  "=r"(r[3]),
          "=r"(r[4]),  "=r"(r[5]),  "=r"(r[6]),  "=r"(r[7]),
          "=r"(r[8]),  "=r"(r[9]),  "=r"(r[10]), "=r"(r[11]),
          "=r"(r[12]), "=r"(r[13]), "=r"(r[14]), "=r"(r[15]),
          "=r"(r[16]), "=r"(r[17]), "=r"(r[18]), "=r"(r[19]),
          "=r"(r[20]), "=r"(r[21]), "=r"(r[22]), "=r"(r[23]),
          "=r"(r[24]), "=r"(r[25]), "=r"(r[26]), "=r"(r[27]),
          "=r"(r[28]), "=r"(r[29]), "=r"(r[30]), "=r"(r[31])
        : "r"(tmem_addr));
}
#endif  // HAS_TCGEN05

// ---------------------------------------------------------------------------
// Kernel 1: fp32 -> fp16 convert of inp, writing chunk-blocked swizzled g_A.
// One thread = one 16B output vector (8 k-values).
// ---------------------------------------------------------------------------
__global__ void __launch_bounds__(256) cvt_inp_kernel(const float4* __restrict__ in) {
    int i = blockIdx.x * 256 + threadIdx.x;     // 0 .. 2M-1
    int m = i >> 9, kv = i & 511;               // kv = 16B-vector index in row
    float4 v0 = in[(size_t)m * 1024 + kv * 2];
    float4 v1 = in[(size_t)m * 1024 + kv * 2 + 1];
    uint4 u;
    u.x = h2u(__floats2half2_rn(v0.x, v0.y));
    u.y = h2u(__floats2half2_rn(v0.z, v0.w));
    u.z = h2u(__floats2half2_rn(v1.x, v1.y));
    u.w = h2u(__floats2half2_rn(v1.z, v1.w));
    uint32_t blk = (uint32_t)(m >> 7) * 64 + (kv >> 3);
    uint32_t off = SWZ((uint32_t)(m & 127) * 128 + (kv & 7) * 16);
    *reinterpret_cast<uint4*>(reinterpret_cast<char*>(g_A) +
                              (size_t)blk * A_BYTES + off) = u;
}

// ---------------------------------------------------------------------------
// Kernel 2: weight transform -> chunk-blocked swizzled g_B.
// W viewed as [4 heads, 1024, 4096]; per-head 3x3 conv (pad 1) + bias
// + sigmoid(sk)*W. One thread = 8 k-values = one 16B output vector.
// ---------------------------------------------------------------------------
__global__ void __launch_bounds__(512) xform_w_kernel(
    const float* __restrict__ W, const float* __restrict__ cw,
    const float* __restrict__ cb, const float* __restrict__ sk) {
    int row = blockIdx.x;          // fout index 0..4095
    int tid = threadIdx.x;         // 0..511
    int c0 = tid * 8;
    int h = row >> 10, r = row & 1023;

    float kk[9];
#pragma unroll
    for (int j = 0; j < 9; ++j) kk[j] = cw[h * 9 + j];
    float bias = cb[h];
    float gate = 1.0f / (1.0f + expf(-sk[h]));

    float acc[8], cen[8];
#pragma unroll
    for (int j = 0; j < 8; ++j) acc[j] = bias;

    const float* base = W + (size_t)(h << 10) * FIN;
#pragma unroll
    for (int dr = -1; dr <= 1; ++dr) {
        int rr = r + dr;
        if (rr < 0 || rr > 1023) continue;
        const float* rp = base + (size_t)rr * FIN;
        float x[10];
        x[0] = (c0 > 0) ? rp[c0 - 1] : 0.f;
        float4 a = *reinterpret_cast<const float4*>(rp + c0);
        float4 b = *reinterpret_cast<const float4*>(rp + c0 + 4);
        x[1] = a.x; x[2] = a.y; x[3] = a.z; x[4] = a.w;
        x[5] = b.x; x[6] = b.y; x[7] = b.z; x[8] = b.w;
        x[9] = (c0 + 8 < FIN) ? rp[c0 + 8] : 0.f;
        if (dr == 0) {
#pragma unroll
            for (int j = 0; j < 8; ++j) cen[j] = x[j + 1];
        }
        int kr = (dr + 1) * 3;
#pragma unroll
        for (int j = 0; j < 8; ++j)
            acc[j] += kk[kr] * x[j] + kk[kr + 1] * x[j + 1] + kk[kr + 2] * x[j + 2];
    }

    uint4 u;
    u.x = h2u(__floats2half2_rn(acc[0] + gate * cen[0], acc[1] + gate * cen[1]));
    u.y = h2u(__floats2half2_rn(acc[2] + gate * cen[2], acc[3] + gate * cen[3]));
    u.z = h2u(__floats2half2_rn(acc[4] + gate * cen[4], acc[5] + gate * cen[5]));
    u.w = h2u(__floats2half2_rn(acc[6] + gate * cen[6], acc[7] + gate * cen[7]));
    uint32_t blk = (uint32_t)(row >> 8) * 64 + (tid >> 3);
    uint32_t off = SWZ((uint32_t)(row & 255) * 128 + (tid & 7) * 16);
    *reinterpret_cast<uint4*>(reinterpret_cast<char*>(g_B) +
                              (size_t)blk * B_BYTES + off) = u;
}

// ---------------------------------------------------------------------------
// Kernel 3: tcgen05 GEMM. 128x256 tile / CTA, 2-stage cp.async.bulk pipeline,
// OCCUPANCY 2 (two CTAs share each SM: one CTA's prologue/epilogue/pipeline
// bubbles are hidden by the other's MMAs; waves drop 3.46 -> 1.94).
// Cluster (2,2): A multicast across the n-pair, B multicast across the m-pair
// (halved L2 traffic is required at occ-2's doubled concurrency).
// out[m,n] = sum_k g_A[m,k] * g_B[n,k], fp32 accumulate in TMEM (256 cols/CTA).
// ---------------------------------------------------------------------------
__global__ void __launch_bounds__(256, 2) __cluster_dims__(2, 2, 1)
gemm_kernel(float* __restrict__ out) {
    extern __shared__ char smem[];
    int tid = threadIdx.x;
    int m0 = blockIdx.y << 7;   // 32 m-tiles (cluster pairs adjacent m)
    int n0 = blockIdx.x << 8;   // 16 n-tiles (cluster pairs adjacent n)

#if HAS_TCGEN05
    uint32_t sb = smem_u32(smem);
    int wid = tid >> 5, lid = tid & 31;
    int cx = blockIdx.x & 1, cy = blockIdx.y & 1;   // rank = cx + 2*cy
    uint16_t maskA = (uint16_t)(0x3u << (2 * cy));  // n-pair, same cy
    uint16_t maskB = (uint16_t)(0x5u << cx);        // m-pair, same cx

    if (tid == 0) {
#pragma unroll
        for (int s = 0; s < NSTAGE; ++s) {
            asm volatile("mbarrier.init.shared.b64 [%0], 1;"
                         :: "r"(sb + SM_BAR + s * 16) : "memory");       // full
            asm volatile("mbarrier.init.shared.b64 [%0], 4;"
                         :: "r"(sb + SM_BAR + s * 16 + 8) : "memory");   // empty
        }
        asm volatile("mbarrier.init.shared.b64 [%0], 1;"
                     :: "r"(sb + SM_DONE) : "memory");
    }
    if (wid == 0) {
        asm volatile("tcgen05.alloc.cta_group::1.sync.aligned.shared::cta.b32 [%0], 256;"
                     :: "r"(sb) : "memory");
        asm volatile("tcgen05.relinquish_alloc_permit.cta_group::1.sync.aligned;");
    }
    __syncthreads();
    // all 4 CTAs' barriers must exist before any multicast targets a peer
    asm volatile("barrier.cluster.arrive.aligned;" ::: "memory");
    asm volatile("barrier.cluster.wait.aligned;" ::: "memory");

    uint32_t tmem;
    asm volatile("ld.shared.b32 %0, [%1];" : "=r"(tmem) : "r"(sb));

    if (wid == 0 && elect_one()) {
        // ---- producer: every CTA arms its local full barrier each stage;
        //      cx==0 CTAs source A for the n-pair, cy==0 CTAs source B for
        //      the m-pair. CTA (1,1) issues no copies at all.
        const char* gAb = reinterpret_cast<const char*>(g_A) +
                          (size_t)(m0 >> 7) * 64 * A_BYTES;
        const char* gBb = reinterpret_cast<const char*>(g_B) +
                          (size_t)(n0 >> 8) * 64 * B_BYTES;
        int eph[NSTAGE] = {0, 0};
        for (int i = 0; i < KCHUNKS; ++i) {
            int s = i & (NSTAGE - 1);
            uint32_t full = sb + SM_BAR + s * 16;
            if (i >= NSTAGE) { wait_parity(full + 8, eph[s]); eph[s] ^= 1; }
            uint32_t dA = sb + SM_TILE0 + s * STAGE_BYTES;
            asm volatile("mbarrier.arrive.expect_tx.shared.b64 _, [%0], %1;"
                         :: "r"(full), "r"((uint32_t)STAGE_BYTES) : "memory");
            if (cx == 0)
                bulk_g2s_mc(dA, gAb + (size_t)i * A_BYTES, A_BYTES, full, maskA);
            if (cy == 0)
                bulk_g2s_mc(dA + A_BYTES, gBb + (size_t)i * B_BYTES,
                            B_BYTES, full, maskB);
        }
    } else if (wid == 1 && elect_one()) {
        // ---- consumer: one thread, MMA issue ----
        int fph[NSTAGE] = {0, 0};
        for (int i = 0; i < KCHUNKS; ++i) {
            int s = i & (NSTAGE - 1);
            uint32_t full = sb + SM_BAR + s * 16;
            wait_parity(full, fph[s]); fph[s] ^= 1;
            uint32_t sA = sb + SM_TILE0 + s * STAGE_BYTES;
            uint64_t ad = make_desc(sA);
            uint64_t bd = make_desc(sA + A_BYTES);
#pragma unroll
            for (int ks = 0; ks < 4; ++ks)     // 4 K=16 steps; +32B per step
                mma_f16_ss(tmem, ad + ks * 2, bd + ks * 2, (uint32_t)(i | ks));
            if (i < KCHUNKS - 1) {
                // free this stage in ALL 4 CTAs once this CTA's MMAs complete
                asm volatile(
                    "tcgen05.commit.cta_group::1.mbarrier::arrive::one."
                    "shared::cluster.multicast::cluster.b64 [%0], %1;"
                    :: "r"(full + 8), "h"((uint16_t)0xF) : "memory");
            } else {
                // final chunk -> local done barrier (single-use, parity 0).
                // accumulator-chain ordering => all prior MMAs complete too.
                asm volatile(
                    "tcgen05.commit.cta_group::1.mbarrier::arrive::one."
                    "shared::cluster.b64 [%0];"
                    :: "r"(sb + SM_DONE) : "memory");
            }
        }
    }

    // all 8 warps: wait for full accumulation
    wait_parity(sb + SM_DONE, 0);
    asm volatile("tcgen05.fence::after_thread_sync;" ::: "memory");
    __syncthreads();

    // Epilogue: warp w reads subpartition (w&3), column half (w>>2).
    // SMEM 32x33 transpose per warp -> coalesced 128B row stores.
    int sp = wid & 3, half = wid >> 2;
    float* scr = reinterpret_cast<float*>(smem + 1024 + wid * 4224);  // 32*33*4
    int col0 = n0 + half * 128;
    int rowb = m0 + sp * 32;
#pragma unroll 1
    for (int cb = 0; cb < 4; ++cb) {
        uint32_t regs[32];
        uint32_t ta = tmem + (uint32_t)(half * 128 + cb * 32) + ((uint32_t)sp << 21);
        ldtm_x32(regs, ta);
        asm volatile("tcgen05.wait::ld.sync.aligned;" ::: "memory");
#pragma unroll
        for (int j = 0; j < 32; ++j) scr[lid * 33 + j] = __uint_as_float(regs[j]);
        __syncwarp();
#pragma unroll 4
        for (int r2 = 0; r2 < 32; ++r2)
            out[(size_t)(rowb + r2) * FOUT + col0 + cb * 32 + lid] = scr[r2 * 33 + lid];
        __syncwarp();
    }
    asm volatile("tcgen05.fence::before_thread_sync;" ::: "memory");
    __syncthreads();
    if (wid == 0) {
        asm volatile("tcgen05.dealloc.cta_group::1.sync.aligned.b32 %0, 256;" :: "r"(tmem));
    }
    // no CTA exits while peer multicasts/commits could still target it
    asm volatile("barrier.cluster.arrive.aligned;" ::: "memory");
    asm volatile("barrier.cluster.wait.aligned;" ::: "memory");

#else  // ---------- FFMA fallback (plain sm_103 pass; correctness safety net) ----
    __half* tA = reinterpret_cast<__half*>(smem + SM_TILE0);            // 128 x 64
    __half* tB = reinterpret_cast<__half*>(smem + SM_TILE0 + A_BYTES);  // 256 x 64
    int tm = tid >> 4, tn = tid & 15;

    float acc[8][16];
#pragma unroll
    for (int r = 0; r < 8; ++r)
#pragma unroll
        for (int c = 0; c < 16; ++c) acc[r][c] = 0.f;

    const uint4* gA4 = reinterpret_cast<const uint4*>(g_A);
    const uint4* gB4 = reinterpret_cast<const uint4*>(g_B);

    for (int i = 0; i < KCHUNKS; ++i) {
        __syncthreads();
        uint32_t blkA = (uint32_t)(m0 >> 7) * 64 + i;
        uint32_t blkB = (uint32_t)(n0 >> 8) * 64 + i;
#pragma unroll
        for (int it = 0; it < 4; ++it) {
            int t = tid + it * 256;
            int r = t >> 3, v = t & 7;
            reinterpret_cast<uint4*>(tA)[r * 8 + v] =
                gA4[(size_t)blkA * 1024 + (SWZ((uint32_t)(r * 128 + v * 16)) >> 4)];
        }
#pragma unroll
        for (int it = 0; it < 8; ++it) {
            int t = tid + it * 256;
            int r = t >> 3, v = t & 7;
            reinterpret_cast<uint4*>(tB)[r * 8 + v] =
                gB4[(size_t)blkB * 2048 + (SWZ((uint32_t)(r * 128 + v * 16)) >> 4)];
        }
        __syncthreads();

        for (int k = 0; k < BK; ++k) {
            float av[8], bv[16];
#pragma unroll
            for (int r = 0; r < 8; ++r) av[r] = __half2float(tA[(tm * 8 + r) * 64 + k]);
#pragma unroll
            for (int c = 0; c < 16; ++c) bv[c] = __half2float(tB[(tn * 16 + c) * 64 + k]);
#pragma unroll
            for (int r = 0; r < 8; ++r)
#pragma unroll
                for (int c = 0; c < 16; ++c) acc[r][c] += av[r] * bv[c];
        }
    }

#pragma unroll
    for (int r = 0; r < 8; ++r)
#pragma unroll
        for (int c = 0; c < 16; ++c)
            out[(size_t)(m0 + tm * 8 + r) * FOUT + n0 + tn * 16 + c] = acc[r][c];
#endif
}

// ---------------------------------------------------------------------------
extern "C" void kernel_launch(void* const* d_in, const int* in_sizes, int n_in,
                              void* d_out, int out_size) {
    const float* inp = (const float*)d_in[0];  // [2, 2048, 4096]
    const float* W   = (const float*)d_in[1];  // [4096, 4096]
    const float* cw  = (const float*)d_in[2];  // [4, 1, 3, 3]
    const float* cb  = (const float*)d_in[3];  // [4]
    const float* sk  = (const float*)d_in[4];  // [4, 1, 1]
    float* out = (float*)d_out;                // [2, 2048, 4096]

    cudaFuncSetAttribute(gemm_kernel,
                         cudaFuncAttributeMaxDynamicSharedMemorySize, SMEM_BYTES);

    cvt_inp_kernel<<<8192, 256>>>((const float4*)inp);
    xform_w_kernel<<<4096, 512>>>(W, cw, cb, sk);
    gemm_kernel<<<dim3(16, 32), 256, SMEM_BYTES>>>(out);
}

// round 10
// speedup vs baseline: 1.1607x; 1.1607x over previous
#include <cuda_runtime.h>
#include <cuda_fp16.h>
#include <cstdint>
#include <cstring>

// Problem dims
#define FIN   4096
#define FOUT  4096
#define MTOT  4096   // 2 * 2048

#define KCHUNKS 64          // K chunks of 64
#define NSTAGE  4
#define A_BYTES      16384  // 128 rows x 128B (this CTA's M-half)
#define BH_BYTES     16384  // one B half: 128 rows x 128B
#define STAGE_BYTES  49152  // A + B0half + B1half
#define TX_BYTES     49152  // per-CTA TMA bytes per stage (tracked per-CTA)

// SMEM layout (dynamic):
//   [0..4)     TMEM base ptr (written by tcgen05.alloc cg2)
//   [8..72)    full[s]=8+16s, empty[s]=16+16s  (s=0..3)
//   [72..80)   done mbarrier
//   [1024 + s*49152) stage s: A(16K) | B0half(16K) | B1half(16K)
#define SM_BAR    8
#define SM_DONE   72
#define SM_TILE0  1024
#define SMEM_BYTES (1024 + NSTAGE * STAGE_BYTES)   // 197632, occupancy 1

// idesc kind::f16 cg2: dtype=F32(1<<4), a/b=F16(0), N=256 -> 32<<17,
// M=256 -> 16<<24
#define IDESC_CG2 0x10400010u
// cluster rank bit in SMEM addresses (Sm100MmaPeerBitMask)
#define PEER_MASK 0xFEFFFFFFu

#if defined(__CUDA_ARCH__) && \
    (defined(__CUDA_ARCH_FEAT_SM103_ALL) || defined(__CUDA_ARCH_FEAT_SM100_ALL) || \
     defined(__CUDA_ARCH_FEAT_SM101_ALL))
#define HAS_TCGEN05 1
#else
#define HAS_TCGEN05 0
#endif

// fp16 staging in chunk-blocked, pre-SW128-swizzled layout:
// g_A: [mtile(32 x 128rows)][chunk(64)][16384B]
// g_B: [ntile(16 x 256rows)][chunk(64)][32768B]; each 16KB half-block is a
//      standalone SW128 128-row image (swizzle is row-local).
__device__ __half g_A[(size_t)MTOT * FIN];
__device__ __half g_B[(size_t)FOUT * FIN];

#define SWZ(x) ((x) ^ (((x) >> 3) & 0x70))

__device__ __forceinline__ uint32_t h2u(__half2 h) {
    uint32_t u; memcpy(&u, &h, 4); return u;
}

__device__ __forceinline__ uint32_t smem_u32(const void* p) {
    uint32_t a;
    asm("{ .reg .u64 t; cvta.to.shared.u64 t, %1; cvt.u32.u64 %0, t; }"
        : "=r"(a) : "l"(p));
    return a;
}

#if HAS_TCGEN05
__device__ __forceinline__ bool elect_one() {
    uint32_t pred;
    asm volatile(
        "{\n\t.reg .pred p;\n\t"
        "elect.sync _|p, 0xFFFFFFFF;\n\t"
        "selp.b32 %0, 1, 0, p;\n\t}"
        : "=r"(pred));
    return pred != 0;
}

// SW128 K-major smem descriptor: layout=SW128(2), version=1, SBO=64, LBO=1
static constexpr unsigned long long DESC_BASE =
    (2ULL << 61) | (1ULL << 46) | (64ULL << 32) | (1ULL << 16);

__device__ __forceinline__ uint64_t make_desc(uint32_t addr) {
    return DESC_BASE | ((uint64_t)(addr >> 4) & 0x3FFF);
}

__device__ __forceinline__ void wait_parity(uint32_t mbar, int phase) {
    asm volatile(
        "{\n\t.reg .pred P;\n\t"
        "WL%=:\n\t"
        "mbarrier.try_wait.parity.acquire.cta.shared::cta.b64 P, [%0], %1, 0x989680;\n\t"
        "@P bra.uni WD%=;\n\t"
        "bra.uni WL%=;\n\t"
        "WD%=:\n\t}"
        :: "r"(mbar), "r"((uint32_t)phase) : "memory");
}

__device__ __forceinline__ void bulk_g2s(uint32_t dst, const void* src,
                                         uint32_t bytes, uint32_t mbar) {
    asm volatile(
        "cp.async.bulk.shared::cluster.global.mbarrier::complete_tx::bytes "
        "[%0], [%1], %2, [%3];"
        :: "r"(dst), "l"(src), "r"(bytes), "r"(mbar) : "memory");
}

__device__ __forceinline__ void mma_f16_ss_cg2(uint32_t d_tmem, uint64_t a_desc,
                                               uint64_t b_desc, uint32_t en) {
    asm volatile(
        "{\n\t.reg .pred p;\n\t"
        "setp.ne.u32 p, %5, 0;\n\t"
        "tcgen05.mma.cta_group::2.kind::f16 [%0], %1, %2, %3, "
        "{%4, %4, %4, %4, %4, %4, %4, %4}, p;\n\t}"
        :: "r"(d_tmem), "l"(a_desc), "l"(b_desc), "r"(IDESC_CG2),
           "r"(0u), "r"(en)
        : "memory");
}

__device__ __forceinline__ void ldtm_x32(uint32_t* r, uint32_t tmem_addr) {
    asm volatile(
        "tcgen05.ld.sync.aligned.32x32b.x32.b32 "
        "{%0, %1, %2, %3, %4, %5, %6, %7, "
        " %8, %9, %10, %11, %12, %13, %14, %15, "
        " %16, %17, %18, %19, %20, %21, %22, %23, "
        " %24, %25, %26, %27, %28, %29, %30, %31}, [%32];"
        : "=r"(r[0]),  "=r"(r[1]),  "=r"(r[2]),  "=r"(r[3]),
          "=r"(r[4]),  "=r"(r[5]),  "=r"(r[6]),  "=r"(r[7]),
          "=r"(r[8]),  "=r"(r[9]),  "=r"(r[10]), "=r"(r[11]),
          "=r"(r[12]), "=r"(r[13]), "=r"(r[14]), "=r"(r[15]),
          "=r"(r[16]), "=r"(r[17]), "=r"(r[18]), "=r"(r[19]),
          "=r"(r[20]), "=r"(r[21]), "=r"(r[22]), "=r"(r[23]),
          "=r"(r[24]), "=r"(r[25]), "=r"(r[26]), "=r"(r[27]),
          "=r"(r[28]), "=r"(r[29]), "=r"(r[30]), "=r"(r[31])
        : "r"(tmem_addr));
}
#endif  // HAS_TCGEN05

// ---------------------------------------------------------------------------
// Kernel 1: fp32 -> fp16 convert of inp -> chunk-blocked swizzled g_A.
// ---------------------------------------------------------------------------
__global__ void __launch_bounds__(256) cvt_inp_kernel(const float4* __restrict__ in) {
    int i = blockIdx.x * 256 + threadIdx.x;     // 0 .. 2M-1
    int m = i >> 9, kv = i & 511;
    float4 v0 = in[(size_t)m * 1024 + kv * 2];
    float4 v1 = in[(size_t)m * 1024 + kv * 2 + 1];
    uint4 u;
    u.x = h2u(__floats2half2_rn(v0.x, v0.y));
    u.y = h2u(__floats2half2_rn(v0.z, v0.w));
    u.z = h2u(__floats2half2_rn(v1.x, v1.y));
    u.w = h2u(__floats2half2_rn(v1.z, v1.w));
    uint32_t blk = (uint32_t)(m >> 7) * 64 + (kv >> 3);
    uint32_t off = SWZ((uint32_t)(m & 127) * 128 + (kv & 7) * 16);
    *reinterpret_cast<uint4*>(reinterpret_cast<char*>(g_A) +
                              (size_t)blk * A_BYTES + off) = u;
}

// ---------------------------------------------------------------------------
// Kernel 2: weight transform -> chunk-blocked swizzled g_B.
// ---------------------------------------------------------------------------
__global__ void __launch_bounds__(512) xform_w_kernel(
    const float* __restrict__ W, const float* __restrict__ cw,
    const float* __restrict__ cb, const float* __restrict__ sk) {
    int row = blockIdx.x;          // fout index 0..4095
    int tid = threadIdx.x;         // 0..511
    int c0 = tid * 8;
    int h = row >> 10, r = row & 1023;

    float kk[9];
#pragma unroll
    for (int j = 0; j < 9; ++j) kk[j] = cw[h * 9 + j];
    float bias = cb[h];
    float gate = 1.0f / (1.0f + expf(-sk[h]));

    float acc[8], cen[8];
#pragma unroll
    for (int j = 0; j < 8; ++j) acc[j] = bias;

    const float* base = W + (size_t)(h << 10) * FIN;
#pragma unroll
    for (int dr = -1; dr <= 1; ++dr) {
        int rr = r + dr;
        if (rr < 0 || rr > 1023) continue;
        const float* rp = base + (size_t)rr * FIN;
        float x[10];
        x[0] = (c0 > 0) ? rp[c0 - 1] : 0.f;
        float4 a = *reinterpret_cast<const float4*>(rp + c0);
        float4 b = *reinterpret_cast<const float4*>(rp + c0 + 4);
        x[1] = a.x; x[2] = a.y; x[3] = a.z; x[4] = a.w;
        x[5] = b.x; x[6] = b.y; x[7] = b.z; x[8] = b.w;
        x[9] = (c0 + 8 < FIN) ? rp[c0 + 8] : 0.f;
        if (dr == 0) {
#pragma unroll
            for (int j = 0; j < 8; ++j) cen[j] = x[j + 1];
        }
        int kr = (dr + 1) * 3;
#pragma unroll
        for (int j = 0; j < 8; ++j)
            acc[j] += kk[kr] * x[j] + kk[kr + 1] * x[j + 1] + kk[kr + 2] * x[j + 2];
    }

    uint4 u;
    u.x = h2u(__floats2half2_rn(acc[0] + gate * cen[0], acc[1] + gate * cen[1]));
    u.y = h2u(__floats2half2_rn(acc[2] + gate * cen[2], acc[3] + gate * cen[3]));
    u.z = h2u(__floats2half2_rn(acc[4] + gate * cen[4], acc[5] + gate * cen[5]));
    u.w = h2u(__floats2half2_rn(acc[6] + gate * cen[6], acc[7] + gate * cen[7]));
    uint32_t blk = (uint32_t)(row >> 8) * 64 + (tid >> 3);
    uint32_t off = SWZ((uint32_t)(row & 255) * 128 + (tid & 7) * 16);
    *reinterpret_cast<uint4*>(reinterpret_cast<char*>(g_B) +
                              (size_t)blk * 32768 + off) = u;
}

// ---------------------------------------------------------------------------
// Kernel 3: cg2 tcgen05 GEMM. CTA-pair computes 256(M) x 512(N); per chunk
// each CTA stages A(16K, its M-half) + two B halves (16K each, its N-split).
// Per-SM SMEM delivery drops 96 -> 48 B/cyc vs the cg1 128x256 design.
// Leader (rank 0) issues 8 cg2 MMAs/chunk (2 N-halves x 4 K-steps) into
// TMEM cols 0/256; follower relays its data-ready via cluster arrive.
// ---------------------------------------------------------------------------
__global__ void __launch_bounds__(256, 1) __cluster_dims__(2, 1, 1)
gemm_kernel(float* __restrict__ out) {
    extern __shared__ char smem[];
    int tid = threadIdx.x;
    int pn = blockIdx.x >> 1;        // 8 n-pairs (512 cols each)
    int rank = blockIdx.x & 1;       // cg2 pair rank
    int pm = blockIdx.y;             // 16 m-pairs (256 rows each)

#if HAS_TCGEN05
    uint32_t sb = smem_u32(smem);
    int wid = tid >> 5, lid = tid & 31;

    if (tid == 0) {
#pragma unroll
        for (int s = 0; s < NSTAGE; ++s) {
            // leader full: expect_tx arrive + follower relay arrive = 2
            asm volatile("mbarrier.init.shared.b64 [%0], %1;"
                         :: "r"(sb + SM_BAR + s * 16),
                            "r"(rank == 0 ? 2u : 1u) : "memory");
            asm volatile("mbarrier.init.shared.b64 [%0], 1;"
                         :: "r"(sb + SM_BAR + s * 16 + 8) : "memory");   // empty
        }
        asm volatile("mbarrier.init.shared.b64 [%0], 1;"
                     :: "r"(sb + SM_DONE) : "memory");
    }
    if (wid == 0) {
        asm volatile("tcgen05.alloc.cta_group::2.sync.aligned.shared::cta.b32 [%0], 512;"
                     :: "r"(sb) : "memory");
        asm volatile("tcgen05.relinquish_alloc_permit.cta_group::2.sync.aligned;");
    }
    __syncthreads();
    // pair barriers must exist before any cross-CTA arrive / commit multicast
    asm volatile("barrier.cluster.arrive.aligned;" ::: "memory");
    asm volatile("barrier.cluster.wait.aligned;" ::: "memory");

    uint32_t tmem;
    asm volatile("ld.shared.b32 %0, [%1];" : "=r"(tmem) : "r"(sb));

    if (wid == 0 && elect_one()) {
        // ---- producer (both ranks): stage own A-half + own two B-splits ----
        const char* gAp = reinterpret_cast<const char*>(g_A) +
                          (size_t)(pm * 2 + rank) * 64 * A_BYTES;
        const char* gB0 = reinterpret_cast<const char*>(g_B) +
                          (size_t)(pn * 2) * 64 * 32768 + (size_t)rank * 16384;
        const char* gB1 = reinterpret_cast<const char*>(g_B) +
                          (size_t)(pn * 2 + 1) * 64 * 32768 + (size_t)rank * 16384;
        int eph[NSTAGE] = {0, 0, 0, 0};
        for (int i = 0; i < KCHUNKS; ++i) {
            int s = i & (NSTAGE - 1);
            uint32_t full = sb + SM_BAR + s * 16;
            if (i >= NSTAGE) { wait_parity(full + 8, eph[s]); eph[s] ^= 1; }
            asm volatile("mbarrier.arrive.expect_tx.shared.b64 _, [%0], %1;"
                         :: "r"(full), "r"((uint32_t)TX_BYTES) : "memory");
            uint32_t dst = sb + SM_TILE0 + s * STAGE_BYTES;
            bulk_g2s(dst,         gAp + (size_t)i * A_BYTES, A_BYTES, full);
            bulk_g2s(dst + 16384, gB0 + (size_t)i * 32768, BH_BYTES, full);
            bulk_g2s(dst + 32768, gB1 + (size_t)i * 32768, BH_BYTES, full);
        }
    } else if (wid == 1 && elect_one()) {
        if (rank == 0) {
            // ---- consumer (leader): 8 cg2 MMAs per chunk ----
            int fph[NSTAGE] = {0, 0, 0, 0};
            for (int i = 0; i < KCHUNKS; ++i) {
                int s = i & (NSTAGE - 1);
                uint32_t full = sb + SM_BAR + s * 16;
                wait_parity(full, fph[s]); fph[s] ^= 1;
                uint32_t sA = sb + SM_TILE0 + s * STAGE_BYTES;
                uint64_t ad  = make_desc(sA);
                uint64_t bd0 = make_desc(sA + 16384);
                uint64_t bd1 = make_desc(sA + 32768);
#pragma unroll
                for (int ks = 0; ks < 4; ++ks) {   // K=16 steps; +32B per step
                    uint32_t en = (uint32_t)(i | ks);
                    mma_f16_ss_cg2(tmem,       ad + ks * 2, bd0 + ks * 2, en);
                    mma_f16_ss_cg2(tmem + 256, ad + ks * 2, bd1 + ks * 2, en);
                }
                if (i < KCHUNKS - 1) {
                    asm volatile(
                        "tcgen05.commit.cta_group::2.mbarrier::arrive::one."
                        "shared::cluster.multicast::cluster.b64 [%0], %1;"
                        :: "r"(full + 8), "h"((uint16_t)0x3) : "memory");
                } else {
                    asm volatile(
                        "tcgen05.commit.cta_group::2.mbarrier::arrive::one."
                        "shared::cluster.multicast::cluster.b64 [%0], %1;"
                        :: "r"(sb + SM_DONE), "h"((uint16_t)0x3) : "memory");
                }
            }
        } else {
            // ---- relay (follower): own data ready -> arrive leader's full ----
            int fph[NSTAGE] = {0, 0, 0, 0};
            for (int i = 0; i < KCHUNKS; ++i) {
                int s = i & (NSTAGE - 1);
                uint32_t full = sb + SM_BAR + s * 16;
                wait_parity(full, fph[s]); fph[s] ^= 1;
                asm volatile("mbarrier.arrive.shared::cluster.b64 _, [%0];"
                             :: "r"(full & PEER_MASK) : "memory");
            }
        }
    }

    // all warps (both CTAs): wait for full accumulation
    wait_parity(sb + SM_DONE, 0);
    asm volatile("tcgen05.fence::after_thread_sync;" ::: "memory");
    __syncthreads();

    // Epilogue: this CTA owns output rows pm*256 + rank*128 .. +128,
    // cols pn*512 .. +512 (TMEM cols 0..511 across its 128 lanes).
    // Warp w: rows (w&3)*32, col segment (w>>2)*256, 8 blocks of 32 cols.
    int sp = wid & 3, halfc = wid >> 2;
    float* scr = reinterpret_cast<float*>(smem + 1024 + wid * 4224);  // 32x33 f32
    int rowb = pm * 256 + rank * 128 + sp * 32;
    int col0 = pn * 512 + halfc * 256;
#pragma unroll 1
    for (int cb = 0; cb < 8; ++cb) {
        uint32_t regs[32];
        uint32_t ta = tmem + (uint32_t)(halfc * 256 + cb * 32) + ((uint32_t)sp << 21);
        ldtm_x32(regs, ta);
        asm volatile("tcgen05.wait::ld.sync.aligned;" ::: "memory");
#pragma unroll
        for (int j = 0; j < 32; ++j) scr[lid * 33 + j] = __uint_as_float(regs[j]);
        __syncwarp();
#pragma unroll 4
        for (int r2 = 0; r2 < 32; ++r2)
            out[(size_t)(rowb + r2) * FOUT + col0 + cb * 32 + lid] = scr[r2 * 33 + lid];
        __syncwarp();
    }
    asm volatile("tcgen05.fence::before_thread_sync;" ::: "memory");
    __syncthreads();
    if (wid == 0) {
        asm volatile("tcgen05.dealloc.cta_group::2.sync.aligned.b32 %0, 512;" :: "r"(tmem));
    }
    // no CTA exits while peer commits/arrives could still target it
    asm volatile("barrier.cluster.arrive.aligned;" ::: "memory");
    asm volatile("barrier.cluster.wait.aligned;" ::: "memory");

#else  // ---------- FFMA fallback (plain sm_103 pass; correctness safety net) ----
    // This CTA covers rows [pm*256 + rank*128, +128), cols [pn*512, +512),
    // processed as two 128x256 passes with smem tiling.
    __half* tA = reinterpret_cast<__half*>(smem + SM_TILE0);            // 128x64
    __half* tB = reinterpret_cast<__half*>(smem + SM_TILE0 + 16384);    // 256x64
    int tm = tid >> 4, tn = tid & 15;
    int mt = pm * 2 + rank;          // A mtile (128 rows)
    int m0f = mt << 7;

    const uint4* gA4 = reinterpret_cast<const uint4*>(g_A);
    const uint4* gB4 = reinterpret_cast<const uint4*>(g_B);

    for (int qn = 0; qn < 2; ++qn) {
        int nt = pn * 2 + qn;        // B ntile (256 rows)
        int n0f = nt << 8;
        float acc[8][16];
#pragma unroll
        for (int r = 0; r < 8; ++r)
#pragma unroll
            for (int c = 0; c < 16; ++c) acc[r][c] = 0.f;

        for (int i = 0; i < KCHUNKS; ++i) {
            __syncthreads();
            uint32_t blkA = (uint32_t)mt * 64 + i;
            uint32_t blkB = (uint32_t)nt * 64 + i;
#pragma unroll
            for (int it = 0; it < 4; ++it) {
                int t = tid + it * 256;
                int r = t >> 3, v = t & 7;
                reinterpret_cast<uint4*>(tA)[r * 8 + v] =
                    gA4[(size_t)blkA * 1024 + (SWZ((uint32_t)(r * 128 + v * 16)) >> 4)];
            }
#pragma unroll
            for (int it = 0; it < 8; ++it) {
                int t = tid + it * 256;
                int r = t >> 3, v = t & 7;
                reinterpret_cast<uint4*>(tB)[r * 8 + v] =
                    gB4[(size_t)blkB * 2048 + (SWZ((uint32_t)(r * 128 + v * 16)) >> 4)];
            }
            __syncthreads();

            for (int k = 0; k < 64; ++k) {
                float av[8], bv[16];
#pragma unroll
                for (int r = 0; r < 8; ++r) av[r] = __half2float(tA[(tm * 8 + r) * 64 + k]);
#pragma unroll
                for (int c = 0; c < 16; ++c) bv[c] = __half2float(tB[(tn * 16 + c) * 64 + k]);
#pragma unroll
                for (int r = 0; r < 8; ++r)
#pragma unroll
                    for (int c = 0; c < 16; ++c) acc[r][c] += av[r] * bv[c];
            }
        }
#pragma unroll
        for (int r = 0; r < 8; ++r)
#pragma unroll
            for (int c = 0; c < 16; ++c)
                out[(size_t)(m0f + tm * 8 + r) * FOUT + n0f + tn * 16 + c] = acc[r][c];
        __syncthreads();
    }
#endif
}

// ---------------------------------------------------------------------------
extern "C" void kernel_launch(void* const* d_in, const int* in_sizes, int n_in,
                              void* d_out, int out_size) {
    const float* inp = (const float*)d_in[0];  // [2, 2048, 4096]
    const float* W   = (const float*)d_in[1];  // [4096, 4096]
    const float* cw  = (const float*)d_in[2];  // [4, 1, 3, 3]
    const float* cb  = (const float*)d_in[3];  // [4]
    const float* sk  = (const float*)d_in[4];  // [4, 1, 1]
    float* out = (float*)d_out;                // [2, 2048, 4096]

    cudaFuncSetAttribute(gemm_kernel,
                         cudaFuncAttributeMaxDynamicSharedMemorySize, SMEM_BYTES);

    cvt_inp_kernel<<<8192, 256>>>((const float4*)inp);
    xform_w_kernel<<<4096, 512>>>(W, cw, cb, sk);
    gemm_kernel<<<dim3(16, 16), 256, SMEM_BYTES>>>(out);
}